// round 15
// baseline (speedup 1.0000x reference)
#include <cuda_runtime.h>
#include <cuda_bf16.h>
#include <math.h>
#include <stdint.h>

#define NN   16384
#define PI_F 3.14159265358979f
#define CUTI (PI_F / 5.0f)

// ---------------- scratch ----------------------------------------------------
__device__ float g_phi[NN * 256];
__device__ float g_v1 [3 * NN * 128];
__device__ float g_Uv [3 * NN * 128];
__device__ float g_Vv [3 * NN * 128];
__device__ float g_x  [NN * 256];
__device__ float g_m  [NN * 384];

// ---------------- packed f32x2 helpers (k_edge) --------------------------------
typedef unsigned long long u64;
__device__ __forceinline__ u64 pk2(float x, float y) {
    u64 r; asm("mov.b64 %0, {%1,%2};" : "=l"(r) : "f"(x), "f"(y)); return r;
}
__device__ __forceinline__ void upk2(float& x, float& y, u64 v) {
    asm("mov.b64 {%0,%1}, %2;" : "=f"(x), "=f"(y) : "l"(v));
}
__device__ __forceinline__ u64 fma2(u64 a, u64 b, u64 c) {
    u64 d; asm("fma.rn.f32x2 %0, %1, %2, %3;" : "=l"(d) : "l"(a), "l"(b), "l"(c)); return d;
}
__device__ __forceinline__ u64 mul2(u64 a, u64 b) {
    u64 d; asm("mul.rn.f32x2 %0, %1, %2;" : "=l"(d) : "l"(a), "l"(b)); return d;
}

// ---------------- bf16 mma helpers ---------------------------------------------
__device__ __forceinline__ uint32_t sptr(const void* p) {
    uint32_t r;
    asm("{ .reg .u64 t; cvta.to.shared.u64 t, %1; cvt.u32.u64 %0, t; }" : "=r"(r) : "l"(p));
    return r;
}
__device__ __forceinline__ void ldsm4(uint32_t& r0, uint32_t& r1, uint32_t& r2, uint32_t& r3,
                                      uint32_t addr) {
    asm volatile("ldmatrix.sync.aligned.m8n8.x4.shared.b16 {%0,%1,%2,%3}, [%4];"
                 : "=r"(r0), "=r"(r1), "=r"(r2), "=r"(r3) : "r"(addr));
}
__device__ __forceinline__ void ldsm4t(uint32_t& r0, uint32_t& r1, uint32_t& r2, uint32_t& r3,
                                       uint32_t addr) {
    asm volatile("ldmatrix.sync.aligned.m8n8.x4.trans.shared.b16 {%0,%1,%2,%3}, [%4];"
                 : "=r"(r0), "=r"(r1), "=r"(r2), "=r"(r3) : "r"(addr));
}
__device__ __forceinline__ void mma_bf16(float& c0, float& c1, float& c2, float& c3,
                                         uint32_t a0, uint32_t a1, uint32_t a2, uint32_t a3,
                                         uint32_t b0, uint32_t b1) {
    asm volatile(
        "mma.sync.aligned.m16n8k16.row.col.f32.bf16.bf16.f32 "
        "{%0,%1,%2,%3}, {%4,%5,%6,%7}, {%8,%9}, {%0,%1,%2,%3};"
        : "+f"(c0), "+f"(c1), "+f"(c2), "+f"(c3)
        : "r"(a0), "r"(a1), "r"(a2), "r"(a3), "r"(b0), "r"(b1));
}
__device__ __forceinline__ uint32_t pack_bf2(__nv_bfloat16 a, __nv_bfloat16 b) {
    __nv_bfloat162 t; t.x = a; t.y = b;
    return *(uint32_t*)&t;
}
__device__ __forceinline__ void split4(float4 v, uint2& H, uint2& L) {
    __nv_bfloat16 h0 = __float2bfloat16_rn(v.x);
    __nv_bfloat16 h1 = __float2bfloat16_rn(v.y);
    __nv_bfloat16 h2 = __float2bfloat16_rn(v.z);
    __nv_bfloat16 h3 = __float2bfloat16_rn(v.w);
    __nv_bfloat16 l0 = __float2bfloat16_rn(v.x - __bfloat162float(h0));
    __nv_bfloat16 l1 = __float2bfloat16_rn(v.y - __bfloat162float(h1));
    __nv_bfloat16 l2 = __float2bfloat16_rn(v.z - __bfloat162float(h2));
    __nv_bfloat16 l3 = __float2bfloat16_rn(v.w - __bfloat162float(h3));
    H.x = pack_bf2(h0, h1); H.y = pack_bf2(h2, h3);
    L.x = pack_bf2(l0, l1); L.y = pack_bf2(l2, l3);
}
__device__ __forceinline__ float silu_f(float x) { return x / (1.0f + __expf(-x)); }

#define APITCH 72     // 144B rows: conflict-free ldsm
#define BPITCH 136    // 272B rows
#define HPITCH 264    // 528B rows

// ---------------- plane GEMM, 512 threads (16 warps, 4m x 4n, 32x32 tiles) ------
// C_k = v1_k @ W_k + b_k, k = blockIdx.z; block tile 128x128, K = 128.
__global__ void __launch_bounds__(512, 2) k_gemm_planes(
        const float* __restrict__ v1, const float* __restrict__ W,
        const float* __restrict__ Bb, float* __restrict__ C) {
    __shared__ __align__(16) __nv_bfloat16 As[128 * APITCH];
    __shared__ __align__(16) __nv_bfloat16 Bs[64 * BPITCH];
    int zk = blockIdx.z;
    const float* A    = v1 + (size_t)zk * NN * 128;
    const float* B    = W  + (size_t)zk * 128 * 128;
    const float* bias = Bb + zk * 128;
    float* Cc         = C  + (size_t)zk * NN * 128;
    int m0 = blockIdx.x * 128;

    int t = threadIdx.x;
    int lane = t & 31, w = t >> 5;
    int wm = (w & 3) * 32, wn = (w >> 2) * 32;

    float acc[2][4][4] = {};

    uint32_t as_base = sptr(As), bs_base = sptr(Bs);
    int alr = lane & 15, alc = (lane >> 4) * 8;
    int blr = lane & 15, blc = (lane >> 4) * 8;

    for (int k0 = 0; k0 < 128; k0 += 32) {
#pragma unroll
        for (int i = 0; i < 2; i++) {
            int lin = t + i * 512;
            int row = lin >> 3, kc = (lin & 7) * 4;
            uint2 H, L;
            split4(*(const float4*)(A + (size_t)(m0 + row) * 128 + k0 + kc), H, L);
            *(uint2*)&As[row * APITCH + kc]      = H;
            *(uint2*)&As[row * APITCH + 32 + kc] = L;
        }
#pragma unroll
        for (int i = 0; i < 2; i++) {
            int lin = t + i * 512;
            int bk = lin >> 5, bn = (lin & 31) * 4;
            uint2 H, L;
            split4(*(const float4*)(B + (size_t)(k0 + bk) * 128 + bn), H, L);
            *(uint2*)&Bs[bk * BPITCH + bn]        = H;
            *(uint2*)&Bs[(32 + bk) * BPITCH + bn] = L;
        }
        __syncthreads();
#pragma unroll
        for (int pass = 0; pass < 3; pass++) {
            int aoff = (pass == 1) ? 32 : 0;
            int boff = (pass == 2) ? 32 : 0;
#pragma unroll
            for (int ks = 0; ks < 2; ks++) {
                uint32_t a[2][4];
#pragma unroll
                for (int mt = 0; mt < 2; mt++) {
                    uint32_t addr = as_base +
                        ((wm + mt * 16 + alr) * APITCH + aoff + ks * 16 + alc) * 2;
                    ldsm4(a[mt][0], a[mt][1], a[mt][2], a[mt][3], addr);
                }
#pragma unroll
                for (int np = 0; np < 2; np++) {
                    uint32_t addr = bs_base +
                        ((boff + ks * 16 + blr) * BPITCH + wn + np * 16 + blc) * 2;
                    uint32_t r0, r1, r2, r3;
                    ldsm4t(r0, r1, r2, r3, addr);
                    int n2i = np * 2;
                    mma_bf16(acc[0][n2i][0], acc[0][n2i][1], acc[0][n2i][2], acc[0][n2i][3],
                             a[0][0], a[0][1], a[0][2], a[0][3], r0, r1);
                    mma_bf16(acc[0][n2i+1][0], acc[0][n2i+1][1], acc[0][n2i+1][2], acc[0][n2i+1][3],
                             a[0][0], a[0][1], a[0][2], a[0][3], r2, r3);
                    mma_bf16(acc[1][n2i][0], acc[1][n2i][1], acc[1][n2i][2], acc[1][n2i][3],
                             a[1][0], a[1][1], a[1][2], a[1][3], r0, r1);
                    mma_bf16(acc[1][n2i+1][0], acc[1][n2i+1][1], acc[1][n2i+1][2], acc[1][n2i+1][3],
                             a[1][0], a[1][1], a[1][2], a[1][3], r2, r3);
                }
            }
        }
        __syncthreads();
    }

    int r = lane >> 2, c2 = (lane & 3) * 2;
#pragma unroll
    for (int mt = 0; mt < 2; mt++) {
        int row0 = m0 + wm + mt * 16 + r;
#pragma unroll
        for (int nt = 0; nt < 4; nt++) {
            int col = wn + nt * 8 + c2;
            float b0 = bias[col], b1 = bias[col + 1];
            float2 o0 = {acc[mt][nt][0] + b0, acc[mt][nt][1] + b1};
            float2 o1 = {acc[mt][nt][2] + b0, acc[mt][nt][3] + b1};
            *(float2*)(Cc + (size_t)row0 * 128 + col)       = o0;
            *(float2*)(Cc + (size_t)(row0 + 8) * 128 + col) = o1;
        }
    }
}

// ---------------- fused 2-layer MLP (R13 version, Vn3 norm fusion) ---------------
__global__ void __launch_bounds__(256) k_fused_mlp(
        const float* __restrict__ A, const int* __restrict__ aidx,
        int K1, int ldA,
        const float* __restrict__ W1, const float* __restrict__ b1,
        const float* __restrict__ W2, int ldW2, const float* __restrict__ b2,
        float* __restrict__ C, int N2, int n2tiles,
        const float* __restrict__ Vn3) {
    extern __shared__ __align__(16) char smraw[];
    __nv_bfloat16* As = (__nv_bfloat16*)smraw;
    __nv_bfloat16* Bs = As + 64 * APITCH;
    __nv_bfloat16* Hs = Bs + 64 * BPITCH;

    int t = threadIdx.x;
    int lane = t & 31, w = t >> 5;
    int wm = (w & 1) * 32, wn = (w >> 1) * 32;
    int m0 = blockIdx.x * 64;

    uint32_t as_base = sptr(As), bs_base = sptr(Bs), hs_base = sptr(Hs);
    int alr = lane & 15, alc = (lane >> 4) * 8;
    int blr = lane & 15, blc = (lane >> 4) * 8;
    int r = lane >> 2, c2 = (lane & 3) * 2;

    float acc[2][4][4] = {};
    for (int k0 = 0; k0 < K1; k0 += 32) {
#pragma unroll
        for (int i = 0; i < 2; i++) {
            int lin = t + i * 256;
            int row = lin >> 3, kc = (lin & 7) * 4;
            float4 v;
            if (Vn3 && k0 < 128) {
                size_t idx = (size_t)(m0 + row) * 128 + k0 + kc;
                float4 a = *(const float4*)(Vn3 + idx);
                float4 b = *(const float4*)(Vn3 + (size_t)NN * 128 + idx);
                float4 c = *(const float4*)(Vn3 + (size_t)2 * NN * 128 + idx);
                v.x = sqrtf(a.x * a.x + b.x * b.x + c.x * c.x);
                v.y = sqrtf(a.y * a.y + b.y * b.y + c.y * c.y);
                v.z = sqrtf(a.z * a.z + b.z * b.z + c.z * c.z);
                v.w = sqrtf(a.w * a.w + b.w * b.w + c.w * c.w);
            } else {
                const float* src = aidx
                    ? A + (size_t)aidx[m0 + row] * ldA + k0 + kc
                    : A + (size_t)(m0 + row) * ldA + k0 + kc;
                v = *(const float4*)src;
            }
            uint2 H, L;
            split4(v, H, L);
            *(uint2*)&As[row * APITCH + kc]      = H;
            *(uint2*)&As[row * APITCH + 32 + kc] = L;
        }
#pragma unroll
        for (int i = 0; i < 4; i++) {
            int lin = t + i * 256;
            int bk = lin >> 5, bn = (lin & 31) * 4;
            uint2 H, L;
            split4(*(const float4*)(W1 + (size_t)(k0 + bk) * 128 + bn), H, L);
            *(uint2*)&Bs[bk * BPITCH + bn]        = H;
            *(uint2*)&Bs[(32 + bk) * BPITCH + bn] = L;
        }
        __syncthreads();
#pragma unroll
        for (int pass = 0; pass < 3; pass++) {
            int aoff = (pass == 1) ? 32 : 0;
            int boff = (pass == 2) ? 32 : 0;
#pragma unroll
            for (int ks = 0; ks < 2; ks++) {
                uint32_t a[2][4];
#pragma unroll
                for (int mt = 0; mt < 2; mt++) {
                    uint32_t addr = as_base +
                        ((wm + mt * 16 + alr) * APITCH + aoff + ks * 16 + alc) * 2;
                    ldsm4(a[mt][0], a[mt][1], a[mt][2], a[mt][3], addr);
                }
#pragma unroll
                for (int np = 0; np < 2; np++) {
                    uint32_t addr = bs_base +
                        ((boff + ks * 16 + blr) * BPITCH + wn + np * 16 + blc) * 2;
                    uint32_t r0, r1, r2, r3;
                    ldsm4t(r0, r1, r2, r3, addr);
                    int n2i = np * 2;
                    mma_bf16(acc[0][n2i][0], acc[0][n2i][1], acc[0][n2i][2], acc[0][n2i][3],
                             a[0][0], a[0][1], a[0][2], a[0][3], r0, r1);
                    mma_bf16(acc[0][n2i+1][0], acc[0][n2i+1][1], acc[0][n2i+1][2], acc[0][n2i+1][3],
                             a[0][0], a[0][1], a[0][2], a[0][3], r2, r3);
                    mma_bf16(acc[1][n2i][0], acc[1][n2i][1], acc[1][n2i][2], acc[1][n2i][3],
                             a[1][0], a[1][1], a[1][2], a[1][3], r0, r1);
                    mma_bf16(acc[1][n2i+1][0], acc[1][n2i+1][1], acc[1][n2i+1][2], acc[1][n2i+1][3],
                             a[1][0], a[1][1], a[1][2], a[1][3], r2, r3);
                }
            }
        }
        __syncthreads();
    }
#pragma unroll
    for (int mt = 0; mt < 2; mt++) {
        int row0 = wm + mt * 16 + r;
#pragma unroll
        for (int nt = 0; nt < 4; nt++) {
            int col = wn + nt * 8 + c2;
            float b0 = b1[col], b1v = b1[col + 1];
            float x0 = silu_f(acc[mt][nt][0] + b0);
            float x1 = silu_f(acc[mt][nt][1] + b1v);
            float x2 = silu_f(acc[mt][nt][2] + b0);
            float x3 = silu_f(acc[mt][nt][3] + b1v);
            __nv_bfloat16 h0 = __float2bfloat16_rn(x0), h1 = __float2bfloat16_rn(x1);
            __nv_bfloat16 h2 = __float2bfloat16_rn(x2), h3 = __float2bfloat16_rn(x3);
            __nv_bfloat16 l0 = __float2bfloat16_rn(x0 - __bfloat162float(h0));
            __nv_bfloat16 l1 = __float2bfloat16_rn(x1 - __bfloat162float(h1));
            __nv_bfloat16 l2 = __float2bfloat16_rn(x2 - __bfloat162float(h2));
            __nv_bfloat16 l3 = __float2bfloat16_rn(x3 - __bfloat162float(h3));
            *(uint32_t*)&Hs[row0 * HPITCH + col]             = pack_bf2(h0, h1);
            *(uint32_t*)&Hs[row0 * HPITCH + 128 + col]       = pack_bf2(l0, l1);
            *(uint32_t*)&Hs[(row0 + 8) * HPITCH + col]       = pack_bf2(h2, h3);
            *(uint32_t*)&Hs[(row0 + 8) * HPITCH + 128 + col] = pack_bf2(l2, l3);
        }
    }
    __syncthreads();

    for (int nt2 = 0; nt2 < n2tiles; nt2++) {
        int nbase = nt2 * 128;
        float acc2[2][4][4] = {};
        for (int k0 = 0; k0 < 128; k0 += 32) {
#pragma unroll
            for (int i = 0; i < 4; i++) {
                int lin = t + i * 256;
                int bk = lin >> 5, bn = (lin & 31) * 4;
                uint2 H, L;
                split4(*(const float4*)(W2 + (size_t)(k0 + bk) * ldW2 + nbase + bn), H, L);
                *(uint2*)&Bs[bk * BPITCH + bn]        = H;
                *(uint2*)&Bs[(32 + bk) * BPITCH + bn] = L;
            }
            __syncthreads();
#pragma unroll
            for (int pass = 0; pass < 3; pass++) {
                int aoffH = (pass == 1) ? 128 : 0;
                int boff  = (pass == 2) ? 32 : 0;
#pragma unroll
                for (int ks = 0; ks < 2; ks++) {
                    uint32_t a[2][4];
#pragma unroll
                    for (int mt = 0; mt < 2; mt++) {
                        uint32_t addr = hs_base +
                            ((wm + mt * 16 + alr) * HPITCH + aoffH + k0 + ks * 16 + alc) * 2;
                        ldsm4(a[mt][0], a[mt][1], a[mt][2], a[mt][3], addr);
                    }
#pragma unroll
                    for (int np = 0; np < 2; np++) {
                        uint32_t addr = bs_base +
                            ((boff + ks * 16 + blr) * BPITCH + wn + np * 16 + blc) * 2;
                        uint32_t r0, r1, r2, r3;
                        ldsm4t(r0, r1, r2, r3, addr);
                        int n2i = np * 2;
                        mma_bf16(acc2[0][n2i][0], acc2[0][n2i][1], acc2[0][n2i][2], acc2[0][n2i][3],
                                 a[0][0], a[0][1], a[0][2], a[0][3], r0, r1);
                        mma_bf16(acc2[0][n2i+1][0], acc2[0][n2i+1][1], acc2[0][n2i+1][2], acc2[0][n2i+1][3],
                                 a[0][0], a[0][1], a[0][2], a[0][3], r2, r3);
                        mma_bf16(acc2[1][n2i][0], acc2[1][n2i][1], acc2[1][n2i][2], acc2[1][n2i][3],
                                 a[1][0], a[1][1], a[1][2], a[1][3], r0, r1);
                        mma_bf16(acc2[1][n2i+1][0], acc2[1][n2i+1][1], acc2[1][n2i+1][2], acc2[1][n2i+1][3],
                                 a[1][0], a[1][1], a[1][2], a[1][3], r2, r3);
                    }
                }
            }
            __syncthreads();
        }
#pragma unroll
        for (int mt = 0; mt < 2; mt++) {
            int row0 = m0 + wm + mt * 16 + r;
#pragma unroll
            for (int nt = 0; nt < 4; nt++) {
                int col = nbase + wn + nt * 8 + c2;
                float b0 = b2[col], b1v = b2[col + 1];
                float2 o0 = {acc2[mt][nt][0] + b0, acc2[mt][nt][1] + b1v};
                float2 o1 = {acc2[mt][nt][2] + b0, acc2[mt][nt][3] + b1v};
                *(float2*)(C + (size_t)row0 * N2 + col)       = o0;
                *(float2*)(C + (size_t)(row0 + 8) * N2 + col) = o1;
            }
        }
    }
}

// ---------------- edge aggregation: one block per MOLECULE -------------------
__global__ void __launch_bounds__(256) k_edge(
        const float* __restrict__ pos, const float* __restrict__ phi,
        const float* __restrict__ w_r, const float* __restrict__ b_r,
        float* __restrict__ x, float* __restrict__ v1) {
    __shared__ float posm[16][3];
    __shared__ float d_s[120];
    __shared__ float inv_s[120];
    __shared__ float unit_s[120][3];
    __shared__ __align__(16) float rbf_s[120][20];
    int mol = blockIdx.x;
    int mb  = mol * 16;
    int t   = threadIdx.x;

    if (t < 48) posm[t / 3][t % 3] = pos[mb * 3 + t];
    __syncthreads();

    {
        int i = t >> 4, j = t & 15;
        if (i < j) {
            float rx = posm[i][0] - posm[j][0];
            float ry = posm[i][1] - posm[j][1];
            float rz = posm[i][2] - posm[j][2];
            float d  = sqrtf(rx * rx + ry * ry + rz * rz);
            float inv = 1.0f / (d + 1e-8f);
            int p = 15 * i - (i * (i - 1)) / 2 + (j - i - 1);
            d_s[p] = d;
            inv_s[p] = inv;
            unit_s[p][0] = rx * inv; unit_s[p][1] = ry * inv; unit_s[p][2] = rz * inv;
        }
    }
    __syncthreads();

    for (int it = t; it < 2400; it += 256) {
        int p = it / 20, k = it % 20;
        rbf_s[p][k] = __sinf((float)(k + 1) * CUTI * d_s[p]) * inv_s[p];
    }
    __syncthreads();

    int c = 128 + t;
    u64 wr2[10];
#pragma unroll
    for (int q = 0; q < 10; q++)
        wr2[q] = pk2(w_r[(2 * q) * 384 + c], w_r[(2 * q + 1) * 384 + c]);
    float brc = b_r[c];
    float wg0 = (brc < 5.0f) ? 0.5f * (cosf(brc * CUTI) + 1.0f) : 0.0f;

    if (t < 128) {
        float aS[16];
#pragma unroll
        for (int j = 0; j < 16; j++) aS[j] = wg0;
#pragma unroll
        for (int i = 0; i < 15; i++) {
#pragma unroll
            for (int j = i + 1; j < 16; j++) {
                int p = 15 * i - (i * (i - 1)) / 2 + (j - i - 1);
                const ulonglong2* r4 = (const ulonglong2*)rbf_s[p];
                u64 acc = mul2(wr2[0], r4[0].x);
                acc = fma2(wr2[1], r4[0].y, acc);
                ulonglong2 rA = r4[1], rB = r4[2], rC = r4[3], rD = r4[4];
                acc = fma2(wr2[2], rA.x, acc); acc = fma2(wr2[3], rA.y, acc);
                acc = fma2(wr2[4], rB.x, acc); acc = fma2(wr2[5], rB.y, acc);
                acc = fma2(wr2[6], rC.x, acc); acc = fma2(wr2[7], rC.y, acc);
                acc = fma2(wr2[8], rD.x, acc); acc = fma2(wr2[9], rD.y, acc);
                float lo, hi; upk2(lo, hi, acc);
                float lin = lo + hi + brc;
                float wg = (lin < 5.0f) ? 0.5f * (__cosf(lin * CUTI) + 1.0f) : 0.0f;
                aS[i] += wg; aS[j] += wg;
            }
        }
#pragma unroll
        for (int j = 0; j < 16; j++)
            x[(size_t)(mb + j) * 256 + 128 + t] = phi[(size_t)(mb + j) * 256 + t] * aS[j];
    } else {
        int f = t - 128;
        float a0[16], a1[16], a2[16];
#pragma unroll
        for (int j = 0; j < 16; j++) { a0[j] = 0.f; a1[j] = 0.f; a2[j] = 0.f; }
#pragma unroll
        for (int i = 0; i < 15; i++) {
#pragma unroll
            for (int j = i + 1; j < 16; j++) {
                int p = 15 * i - (i * (i - 1)) / 2 + (j - i - 1);
                const ulonglong2* r4 = (const ulonglong2*)rbf_s[p];
                u64 acc = mul2(wr2[0], r4[0].x);
                acc = fma2(wr2[1], r4[0].y, acc);
                ulonglong2 rA = r4[1], rB = r4[2], rC = r4[3], rD = r4[4];
                acc = fma2(wr2[2], rA.x, acc); acc = fma2(wr2[3], rA.y, acc);
                acc = fma2(wr2[4], rB.x, acc); acc = fma2(wr2[5], rB.y, acc);
                acc = fma2(wr2[6], rC.x, acc); acc = fma2(wr2[7], rC.y, acc);
                acc = fma2(wr2[8], rD.x, acc); acc = fma2(wr2[9], rD.y, acc);
                float lo, hi; upk2(lo, hi, acc);
                float lin = lo + hi + brc;
                float wg = (lin < 5.0f) ? 0.5f * (__cosf(lin * CUTI) + 1.0f) : 0.0f;
                float u0 = unit_s[p][0], u1 = unit_s[p][1], u2 = unit_s[p][2];
                a0[j] = fmaf(wg, u0, a0[j]);  a0[i] = fmaf(-wg, u0, a0[i]);
                a1[j] = fmaf(wg, u1, a1[j]);  a1[i] = fmaf(-wg, u1, a1[i]);
                a2[j] = fmaf(wg, u2, a2[j]);  a2[i] = fmaf(-wg, u2, a2[i]);
            }
        }
#pragma unroll
        for (int j = 0; j < 16; j++) {
            float p3 = phi[(size_t)(mb + j) * 256 + 128 + f];
            v1[(size_t)(0 * NN + mb + j) * 128 + f] = p3 * a0[j];
            v1[(size_t)(1 * NN + mb + j) * 128 + f] = p3 * a1[j];
            v1[(size_t)(2 * NN + mb + j) * 128 + f] = p3 * a2[j];
        }
    }
}

// ---------------- final epilogue (float4 vectorized) ----------------------------
__global__ void k_final(const float* __restrict__ m,
                        const float* __restrict__ Uv,
                        const float* __restrict__ Vv,
                        float* __restrict__ out) {
    __shared__ float dvs[3072];
    int t = threadIdx.x;
    size_t i4 = (size_t)blockIdx.x * 256 + t;
    size_t i  = i4 * 4;
    int n = (int)(i >> 7), f = (int)(i & 127);
    const float* mrow = m + (size_t)n * 384 + f;
    float4 avv = *(const float4*)(mrow);
    float4 asv = *(const float4*)(mrow + 128);
    float4 ass = *(const float4*)(mrow + 256);
    float4 u0 = *(const float4*)(Uv + i);
    float4 u1 = *(const float4*)(Uv + (size_t)NN * 128 + i);
    float4 u2 = *(const float4*)(Uv + (size_t)2 * NN * 128 + i);
    float4 v0 = *(const float4*)(Vv + i);
    float4 v1 = *(const float4*)(Vv + (size_t)NN * 128 + i);
    float4 v2 = *(const float4*)(Vv + (size_t)2 * NN * 128 + i);

    float4 os;
    os.x = (u0.x * v0.x + u1.x * v1.x + u2.x * v2.x) * asv.x + ass.x;
    os.y = (u0.y * v0.y + u1.y * v1.y + u2.y * v2.y) * asv.y + ass.y;
    os.z = (u0.z * v0.z + u1.z * v1.z + u2.z * v2.z) * asv.z + ass.z;
    os.w = (u0.w * v0.w + u1.w * v1.w + u2.w * v2.w) * asv.w + ass.w;
    *(float4*)(out + i) = os;

    int li = t * 12;
    dvs[li + 0]  = avv.x * u0.x;  dvs[li + 1]  = avv.x * u1.x;  dvs[li + 2]  = avv.x * u2.x;
    dvs[li + 3]  = avv.y * u0.y;  dvs[li + 4]  = avv.y * u1.y;  dvs[li + 5]  = avv.y * u2.y;
    dvs[li + 6]  = avv.z * u0.z;  dvs[li + 7]  = avv.z * u1.z;  dvs[li + 8]  = avv.z * u2.z;
    dvs[li + 9]  = avv.w * u0.w;  dvs[li + 10] = avv.w * u1.w;  dvs[li + 11] = avv.w * u2.w;
    __syncthreads();

    const float4* dv4 = (const float4*)dvs;
    float* base = out + (size_t)NN * 128 + (size_t)blockIdx.x * 3072;
    *(float4*)(base + t * 4)        = dv4[t];
    *(float4*)(base + 1024 + t * 4) = dv4[256 + t];
    *(float4*)(base + 2048 + t * 4) = dv4[512 + t];
}

// ---------------- launch --------------------------------------------------------
extern "C" void kernel_launch(void* const* d_in, const int* in_sizes, int n_in,
                              void* d_out, int out_size) {
    const int*   atoms = (const int*)  d_in[0];
    const float* pos   = (const float*)d_in[1];
    const float* embed = (const float*)d_in[4];
    const float* w_s1  = (const float*)d_in[5];
    const float* b_s1  = (const float*)d_in[6];
    const float* w_s2  = (const float*)d_in[7];
    const float* b_s2  = (const float*)d_in[8];
    const float* w_r   = (const float*)d_in[9];
    const float* b_r   = (const float*)d_in[10];
    const float* w_u1  = (const float*)d_in[11];
    const float* b_u1  = (const float*)d_in[12];
    const float* w_u2  = (const float*)d_in[13];
    const float* b_u2  = (const float*)d_in[14];
    const float* Uw    = (const float*)d_in[15];
    const float* Ub    = (const float*)d_in[16];
    const float* Vw    = (const float*)d_in[17];
    const float* Vb    = (const float*)d_in[18];
    float* out = (float*)d_out;

    float *phi, *v1, *Uv, *Vv, *x, *mm;
    cudaGetSymbolAddress((void**)&phi, g_phi);
    cudaGetSymbolAddress((void**)&v1,  g_v1);
    cudaGetSymbolAddress((void**)&Uv,  g_Uv);
    cudaGetSymbolAddress((void**)&Vv,  g_Vv);
    cudaGetSymbolAddress((void**)&x,   g_x);
    cudaGetSymbolAddress((void**)&mm,  g_m);

    const int FUSED_SMEM = (64 * APITCH + 64 * BPITCH + 64 * HPITCH) * 2;
    cudaFuncSetAttribute(k_fused_mlp, cudaFuncAttributeMaxDynamicSharedMemorySize,
                         FUSED_SMEM);

    cudaStream_t s2;
    cudaStreamCreateWithFlags(&s2, cudaStreamNonBlocking);
    cudaEvent_t evFork, evJoin;
    cudaEventCreateWithFlags(&evFork, cudaEventDisableTiming);
    cudaEventCreateWithFlags(&evJoin, cudaEventDisableTiming);

    // 1) phi = silu(embed[atoms] @ w_s1 + b_s1) @ w_s2[:,128:384] + b_s2[128:384]
    k_fused_mlp<<<NN / 64, 256, FUSED_SMEM>>>(
        embed, atoms, 128, 128, w_s1, b_s1, w_s2 + 128, 384, b_s2 + 128,
        phi, 256, 2, nullptr);
    // 2) edge aggregation (writes v1 planes + x[:,128:] = s1)
    k_edge<<<NN / 16, 256>>>(pos, phi, w_r, b_r, x, v1);

    // fork: U-plane GEMMs on s2 (consumed only by k_final)
    cudaEventRecord(evFork, 0);
    cudaStreamWaitEvent(s2, evFork, 0);
    k_gemm_planes<<<dim3(NN / 128, 1, 3), 512, 0, s2>>>(v1, Uw, Ub, Uv);

    // main branch: V-plane GEMMs -> gating MLP (norm fused into staging)
    k_gemm_planes<<<dim3(NN / 128, 1, 3), 512>>>(v1, Vw, Vb, Vv);
    k_fused_mlp<<<NN / 64, 256, FUSED_SMEM>>>(
        x, nullptr, 256, 256, w_u1, b_u1, w_u2, 384, b_u2,
        mm, 384, 3, Vv);

    // join, then epilogue (vectorized)
    cudaEventRecord(evJoin, s2);
    cudaStreamWaitEvent(0, evJoin, 0);
    k_final<<<NN * 128 / 1024, 256>>>(mm, Uv, Vv, out);

    cudaEventDestroy(evFork);
    cudaEventDestroy(evJoin);
    cudaStreamDestroy(s2);
}

// round 16
// speedup vs baseline: 1.1581x; 1.1581x over previous
#include <cuda_runtime.h>
#include <cuda_bf16.h>
#include <math.h>
#include <stdint.h>

#define NN   16384
#define PI_F 3.14159265358979f
#define CUTI (PI_F / 5.0f)

// ---------------- scratch ----------------------------------------------------
__device__ float g_phi[NN * 256];       // compact: cols 128..384 of lin phi
__device__ float g_v1 [3 * NN * 128];
__device__ float g_Uv [3 * NN * 128];
__device__ float g_Vv [3 * NN * 128];
__device__ float g_x  [NN * 256];       // only cols 128..256 (s1) used
__device__ float g_m  [NN * 384];

// ---------------- packed f32x2 helpers (k_edge) --------------------------------
typedef unsigned long long u64;
__device__ __forceinline__ u64 pk2(float x, float y) {
    u64 r; asm("mov.b64 %0, {%1,%2};" : "=l"(r) : "f"(x), "f"(y)); return r;
}
__device__ __forceinline__ void upk2(float& x, float& y, u64 v) {
    asm("mov.b64 {%0,%1}, %2;" : "=f"(x), "=f"(y) : "l"(v));
}
__device__ __forceinline__ u64 fma2(u64 a, u64 b, u64 c) {
    u64 d; asm("fma.rn.f32x2 %0, %1, %2, %3;" : "=l"(d) : "l"(a), "l"(b), "l"(c)); return d;
}
__device__ __forceinline__ u64 mul2(u64 a, u64 b) {
    u64 d; asm("mul.rn.f32x2 %0, %1, %2;" : "=l"(d) : "l"(a), "l"(b)); return d;
}

// ---------------- bf16 mma helpers ---------------------------------------------
__device__ __forceinline__ uint32_t sptr(const void* p) {
    uint32_t r;
    asm("{ .reg .u64 t; cvta.to.shared.u64 t, %1; cvt.u32.u64 %0, t; }" : "=r"(r) : "l"(p));
    return r;
}
__device__ __forceinline__ void ldsm4(uint32_t& r0, uint32_t& r1, uint32_t& r2, uint32_t& r3,
                                      uint32_t addr) {
    asm volatile("ldmatrix.sync.aligned.m8n8.x4.shared.b16 {%0,%1,%2,%3}, [%4];"
                 : "=r"(r0), "=r"(r1), "=r"(r2), "=r"(r3) : "r"(addr));
}
__device__ __forceinline__ void ldsm4t(uint32_t& r0, uint32_t& r1, uint32_t& r2, uint32_t& r3,
                                       uint32_t addr) {
    asm volatile("ldmatrix.sync.aligned.m8n8.x4.trans.shared.b16 {%0,%1,%2,%3}, [%4];"
                 : "=r"(r0), "=r"(r1), "=r"(r2), "=r"(r3) : "r"(addr));
}
__device__ __forceinline__ void mma_bf16(float& c0, float& c1, float& c2, float& c3,
                                         uint32_t a0, uint32_t a1, uint32_t a2, uint32_t a3,
                                         uint32_t b0, uint32_t b1) {
    asm volatile(
        "mma.sync.aligned.m16n8k16.row.col.f32.bf16.bf16.f32 "
        "{%0,%1,%2,%3}, {%4,%5,%6,%7}, {%8,%9}, {%0,%1,%2,%3};"
        : "+f"(c0), "+f"(c1), "+f"(c2), "+f"(c3)
        : "r"(a0), "r"(a1), "r"(a2), "r"(a3), "r"(b0), "r"(b1));
}
__device__ __forceinline__ uint32_t pack_bf2(__nv_bfloat16 a, __nv_bfloat16 b) {
    __nv_bfloat162 t; t.x = a; t.y = b;
    return *(uint32_t*)&t;
}
__device__ __forceinline__ void split4(float4 v, uint2& H, uint2& L) {
    __nv_bfloat16 h0 = __float2bfloat16_rn(v.x);
    __nv_bfloat16 h1 = __float2bfloat16_rn(v.y);
    __nv_bfloat16 h2 = __float2bfloat16_rn(v.z);
    __nv_bfloat16 h3 = __float2bfloat16_rn(v.w);
    __nv_bfloat16 l0 = __float2bfloat16_rn(v.x - __bfloat162float(h0));
    __nv_bfloat16 l1 = __float2bfloat16_rn(v.y - __bfloat162float(h1));
    __nv_bfloat16 l2 = __float2bfloat16_rn(v.z - __bfloat162float(h2));
    __nv_bfloat16 l3 = __float2bfloat16_rn(v.w - __bfloat162float(h3));
    H.x = pack_bf2(h0, h1); H.y = pack_bf2(h2, h3);
    L.x = pack_bf2(l0, l1); L.y = pack_bf2(l2, l3);
}
__device__ __forceinline__ float silu_f(float x) { return x / (1.0f + __expf(-x)); }

#define APITCH 72     // 144B rows: conflict-free ldsm
#define BPITCH 136    // 272B rows
#define HPITCH 264    // 528B rows

// ---------------- bf16x3 GEMM body (R13 256-thread version) ---------------------
__device__ __forceinline__ void gemm_body(
        const float* __restrict__ A,
        const float* __restrict__ B, const float* __restrict__ bias,
        float* __restrict__ C, int K, int N, int m0, int n0) {
    __shared__ __align__(16) __nv_bfloat16 As[128 * APITCH];
    __shared__ __align__(16) __nv_bfloat16 Bs[64 * BPITCH];
    int t = threadIdx.x;
    int lane = t & 31, w = t >> 5;
    int wm = (w & 3) * 32, wn = (w >> 2) * 64;

    float acc[2][8][4] = {};

    uint32_t as_base = sptr(As), bs_base = sptr(Bs);
    int alr = lane & 15, alc = (lane >> 4) * 8;
    int blr = lane & 15, blc = (lane >> 4) * 8;

    for (int k0 = 0; k0 < K; k0 += 32) {
#pragma unroll
        for (int i = 0; i < 4; i++) {
            int lin = t + i * 256;
            int row = lin >> 3, kc = (lin & 7) * 4;
            uint2 H, L;
            split4(*(const float4*)(A + (size_t)(m0 + row) * K + k0 + kc), H, L);
            *(uint2*)&As[row * APITCH + kc]      = H;
            *(uint2*)&As[row * APITCH + 32 + kc] = L;
        }
#pragma unroll
        for (int i = 0; i < 4; i++) {
            int lin = t + i * 256;
            int bk = lin >> 5, bn = (lin & 31) * 4;
            uint2 H, L;
            split4(*(const float4*)(B + (size_t)(k0 + bk) * N + n0 + bn), H, L);
            *(uint2*)&Bs[bk * BPITCH + bn]      = H;
            *(uint2*)&Bs[(32 + bk) * BPITCH + bn] = L;
        }
        __syncthreads();
#pragma unroll
        for (int pass = 0; pass < 3; pass++) {
            int aoff = (pass == 1) ? 32 : 0;
            int boff = (pass == 2) ? 32 : 0;
#pragma unroll
            for (int ks = 0; ks < 2; ks++) {
                uint32_t a[2][4];
#pragma unroll
                for (int mt = 0; mt < 2; mt++) {
                    uint32_t addr = as_base +
                        ((wm + mt * 16 + alr) * APITCH + aoff + ks * 16 + alc) * 2;
                    ldsm4(a[mt][0], a[mt][1], a[mt][2], a[mt][3], addr);
                }
                uint32_t b[8][2];
#pragma unroll
                for (int np = 0; np < 4; np++) {
                    uint32_t addr = bs_base +
                        ((boff + ks * 16 + blr) * BPITCH + wn + np * 16 + blc) * 2;
                    uint32_t r0, r1, r2, r3;
                    ldsm4t(r0, r1, r2, r3, addr);
                    b[np * 2][0] = r0;     b[np * 2][1] = r1;
                    b[np * 2 + 1][0] = r2; b[np * 2 + 1][1] = r3;
                }
#pragma unroll
                for (int mt = 0; mt < 2; mt++)
#pragma unroll
                    for (int nt = 0; nt < 8; nt++)
                        mma_bf16(acc[mt][nt][0], acc[mt][nt][1],
                                 acc[mt][nt][2], acc[mt][nt][3],
                                 a[mt][0], a[mt][1], a[mt][2], a[mt][3],
                                 b[nt][0], b[nt][1]);
            }
        }
        __syncthreads();
    }

    int r = lane >> 2, c2 = (lane & 3) * 2;
#pragma unroll
    for (int mt = 0; mt < 2; mt++) {
        int row0 = m0 + wm + mt * 16 + r;
#pragma unroll
        for (int nt = 0; nt < 8; nt++) {
            int col = wn + nt * 8 + c2;
            float b0 = bias[col], b1 = bias[col + 1];
            float2 o0 = {acc[mt][nt][0] + b0, acc[mt][nt][1] + b1};
            float2 o1 = {acc[mt][nt][2] + b0, acc[mt][nt][3] + b1};
            *(float2*)(C + (size_t)row0 * N + col)       = o0;
            *(float2*)(C + (size_t)(row0 + 8) * N + col) = o1;
        }
    }
}

// three plane GEMMs for one weight family (U or V): grid (M/128, 1, 3)
__global__ void __launch_bounds__(256, 2) k_gemm_planes(
        const float* __restrict__ v1, const float* __restrict__ W,
        const float* __restrict__ Bb, float* __restrict__ C) {
    int k = blockIdx.z;
    gemm_body(v1 + (size_t)k * NN * 128, W + (size_t)k * 128 * 128,
              Bb + k * 128, C + (size_t)k * NN * 128, 128, 128,
              blockIdx.x * 128, 0);
}

// ---------------- fused 2-layer MLP (R13 version, Vn3 norm fusion) ---------------
__global__ void __launch_bounds__(256) k_fused_mlp(
        const float* __restrict__ A, const int* __restrict__ aidx,
        int K1, int ldA,
        const float* __restrict__ W1, const float* __restrict__ b1,
        const float* __restrict__ W2, int ldW2, const float* __restrict__ b2,
        float* __restrict__ C, int N2, int n2tiles,
        const float* __restrict__ Vn3) {
    extern __shared__ __align__(16) char smraw[];
    __nv_bfloat16* As = (__nv_bfloat16*)smraw;
    __nv_bfloat16* Bs = As + 64 * APITCH;
    __nv_bfloat16* Hs = Bs + 64 * BPITCH;

    int t = threadIdx.x;
    int lane = t & 31, w = t >> 5;
    int wm = (w & 1) * 32, wn = (w >> 1) * 32;
    int m0 = blockIdx.x * 64;

    uint32_t as_base = sptr(As), bs_base = sptr(Bs), hs_base = sptr(Hs);
    int alr = lane & 15, alc = (lane >> 4) * 8;
    int blr = lane & 15, blc = (lane >> 4) * 8;
    int r = lane >> 2, c2 = (lane & 3) * 2;

    float acc[2][4][4] = {};
    for (int k0 = 0; k0 < K1; k0 += 32) {
#pragma unroll
        for (int i = 0; i < 2; i++) {
            int lin = t + i * 256;
            int row = lin >> 3, kc = (lin & 7) * 4;
            float4 v;
            if (Vn3 && k0 < 128) {
                size_t idx = (size_t)(m0 + row) * 128 + k0 + kc;
                float4 a = *(const float4*)(Vn3 + idx);
                float4 b = *(const float4*)(Vn3 + (size_t)NN * 128 + idx);
                float4 c = *(const float4*)(Vn3 + (size_t)2 * NN * 128 + idx);
                v.x = sqrtf(a.x * a.x + b.x * b.x + c.x * c.x);
                v.y = sqrtf(a.y * a.y + b.y * b.y + c.y * c.y);
                v.z = sqrtf(a.z * a.z + b.z * b.z + c.z * c.z);
                v.w = sqrtf(a.w * a.w + b.w * b.w + c.w * c.w);
            } else {
                const float* src = aidx
                    ? A + (size_t)aidx[m0 + row] * ldA + k0 + kc
                    : A + (size_t)(m0 + row) * ldA + k0 + kc;
                v = *(const float4*)src;
            }
            uint2 H, L;
            split4(v, H, L);
            *(uint2*)&As[row * APITCH + kc]      = H;
            *(uint2*)&As[row * APITCH + 32 + kc] = L;
        }
#pragma unroll
        for (int i = 0; i < 4; i++) {
            int lin = t + i * 256;
            int bk = lin >> 5, bn = (lin & 31) * 4;
            uint2 H, L;
            split4(*(const float4*)(W1 + (size_t)(k0 + bk) * 128 + bn), H, L);
            *(uint2*)&Bs[bk * BPITCH + bn]        = H;
            *(uint2*)&Bs[(32 + bk) * BPITCH + bn] = L;
        }
        __syncthreads();
#pragma unroll
        for (int pass = 0; pass < 3; pass++) {
            int aoff = (pass == 1) ? 32 : 0;
            int boff = (pass == 2) ? 32 : 0;
#pragma unroll
            for (int ks = 0; ks < 2; ks++) {
                uint32_t a[2][4];
#pragma unroll
                for (int mt = 0; mt < 2; mt++) {
                    uint32_t addr = as_base +
                        ((wm + mt * 16 + alr) * APITCH + aoff + ks * 16 + alc) * 2;
                    ldsm4(a[mt][0], a[mt][1], a[mt][2], a[mt][3], addr);
                }
#pragma unroll
                for (int np = 0; np < 2; np++) {
                    uint32_t addr = bs_base +
                        ((boff + ks * 16 + blr) * BPITCH + wn + np * 16 + blc) * 2;
                    uint32_t r0, r1, r2, r3;
                    ldsm4t(r0, r1, r2, r3, addr);
                    int n2i = np * 2;
                    mma_bf16(acc[0][n2i][0], acc[0][n2i][1], acc[0][n2i][2], acc[0][n2i][3],
                             a[0][0], a[0][1], a[0][2], a[0][3], r0, r1);
                    mma_bf16(acc[0][n2i+1][0], acc[0][n2i+1][1], acc[0][n2i+1][2], acc[0][n2i+1][3],
                             a[0][0], a[0][1], a[0][2], a[0][3], r2, r3);
                    mma_bf16(acc[1][n2i][0], acc[1][n2i][1], acc[1][n2i][2], acc[1][n2i][3],
                             a[1][0], a[1][1], a[1][2], a[1][3], r0, r1);
                    mma_bf16(acc[1][n2i+1][0], acc[1][n2i+1][1], acc[1][n2i+1][2], acc[1][n2i+1][3],
                             a[1][0], a[1][1], a[1][2], a[1][3], r2, r3);
                }
            }
        }
        __syncthreads();
    }
#pragma unroll
    for (int mt = 0; mt < 2; mt++) {
        int row0 = wm + mt * 16 + r;
#pragma unroll
        for (int nt = 0; nt < 4; nt++) {
            int col = wn + nt * 8 + c2;
            float b0 = b1[col], b1v = b1[col + 1];
            float x0 = silu_f(acc[mt][nt][0] + b0);
            float x1 = silu_f(acc[mt][nt][1] + b1v);
            float x2 = silu_f(acc[mt][nt][2] + b0);
            float x3 = silu_f(acc[mt][nt][3] + b1v);
            __nv_bfloat16 h0 = __float2bfloat16_rn(x0), h1 = __float2bfloat16_rn(x1);
            __nv_bfloat16 h2 = __float2bfloat16_rn(x2), h3 = __float2bfloat16_rn(x3);
            __nv_bfloat16 l0 = __float2bfloat16_rn(x0 - __bfloat162float(h0));
            __nv_bfloat16 l1 = __float2bfloat16_rn(x1 - __bfloat162float(h1));
            __nv_bfloat16 l2 = __float2bfloat16_rn(x2 - __bfloat162float(h2));
            __nv_bfloat16 l3 = __float2bfloat16_rn(x3 - __bfloat162float(h3));
            *(uint32_t*)&Hs[row0 * HPITCH + col]             = pack_bf2(h0, h1);
            *(uint32_t*)&Hs[row0 * HPITCH + 128 + col]       = pack_bf2(l0, l1);
            *(uint32_t*)&Hs[(row0 + 8) * HPITCH + col]       = pack_bf2(h2, h3);
            *(uint32_t*)&Hs[(row0 + 8) * HPITCH + 128 + col] = pack_bf2(l2, l3);
        }
    }
    __syncthreads();

    for (int nt2 = 0; nt2 < n2tiles; nt2++) {
        int nbase = nt2 * 128;
        float acc2[2][4][4] = {};
        for (int k0 = 0; k0 < 128; k0 += 32) {
#pragma unroll
            for (int i = 0; i < 4; i++) {
                int lin = t + i * 256;
                int bk = lin >> 5, bn = (lin & 31) * 4;
                uint2 H, L;
                split4(*(const float4*)(W2 + (size_t)(k0 + bk) * ldW2 + nbase + bn), H, L);
                *(uint2*)&Bs[bk * BPITCH + bn]        = H;
                *(uint2*)&Bs[(32 + bk) * BPITCH + bn] = L;
            }
            __syncthreads();
#pragma unroll
            for (int pass = 0; pass < 3; pass++) {
                int aoffH = (pass == 1) ? 128 : 0;
                int boff  = (pass == 2) ? 32 : 0;
#pragma unroll
                for (int ks = 0; ks < 2; ks++) {
                    uint32_t a[2][4];
#pragma unroll
                    for (int mt = 0; mt < 2; mt++) {
                        uint32_t addr = hs_base +
                            ((wm + mt * 16 + alr) * HPITCH + aoffH + k0 + ks * 16 + alc) * 2;
                        ldsm4(a[mt][0], a[mt][1], a[mt][2], a[mt][3], addr);
                    }
#pragma unroll
                    for (int np = 0; np < 2; np++) {
                        uint32_t addr = bs_base +
                            ((boff + ks * 16 + blr) * BPITCH + wn + np * 16 + blc) * 2;
                        uint32_t r0, r1, r2, r3;
                        ldsm4t(r0, r1, r2, r3, addr);
                        int n2i = np * 2;
                        mma_bf16(acc2[0][n2i][0], acc2[0][n2i][1], acc2[0][n2i][2], acc2[0][n2i][3],
                                 a[0][0], a[0][1], a[0][2], a[0][3], r0, r1);
                        mma_bf16(acc2[0][n2i+1][0], acc2[0][n2i+1][1], acc2[0][n2i+1][2], acc2[0][n2i+1][3],
                                 a[0][0], a[0][1], a[0][2], a[0][3], r2, r3);
                        mma_bf16(acc2[1][n2i][0], acc2[1][n2i][1], acc2[1][n2i][2], acc2[1][n2i][3],
                                 a[1][0], a[1][1], a[1][2], a[1][3], r0, r1);
                        mma_bf16(acc2[1][n2i+1][0], acc2[1][n2i+1][1], acc2[1][n2i+1][2], acc2[1][n2i+1][3],
                                 a[1][0], a[1][1], a[1][2], a[1][3], r2, r3);
                    }
                }
            }
            __syncthreads();
        }
#pragma unroll
        for (int mt = 0; mt < 2; mt++) {
            int row0 = m0 + wm + mt * 16 + r;
#pragma unroll
            for (int nt = 0; nt < 4; nt++) {
                int col = nbase + wn + nt * 8 + c2;
                float b0 = b2[col], b1v = b2[col + 1];
                float2 o0 = {acc2[mt][nt][0] + b0, acc2[mt][nt][1] + b1v};
                float2 o1 = {acc2[mt][nt][2] + b0, acc2[mt][nt][3] + b1v};
                *(float2*)(C + (size_t)row0 * N2 + col)       = o0;
                *(float2*)(C + (size_t)(row0 + 8) * N2 + col) = o1;
            }
        }
    }
}

// ---------------- edge aggregation: one block per MOLECULE -------------------
__global__ void __launch_bounds__(256) k_edge(
        const float* __restrict__ pos, const float* __restrict__ phi,
        const float* __restrict__ w_r, const float* __restrict__ b_r,
        float* __restrict__ x, float* __restrict__ v1) {
    __shared__ float posm[16][3];
    __shared__ float d_s[120];
    __shared__ float inv_s[120];
    __shared__ float unit_s[120][3];
    __shared__ __align__(16) float rbf_s[120][20];
    int mol = blockIdx.x;
    int mb  = mol * 16;
    int t   = threadIdx.x;

    if (t < 48) posm[t / 3][t % 3] = pos[mb * 3 + t];
    __syncthreads();

    {
        int i = t >> 4, j = t & 15;
        if (i < j) {
            float rx = posm[i][0] - posm[j][0];
            float ry = posm[i][1] - posm[j][1];
            float rz = posm[i][2] - posm[j][2];
            float d  = sqrtf(rx * rx + ry * ry + rz * rz);
            float inv = 1.0f / (d + 1e-8f);
            int p = 15 * i - (i * (i - 1)) / 2 + (j - i - 1);
            d_s[p] = d;
            inv_s[p] = inv;
            unit_s[p][0] = rx * inv; unit_s[p][1] = ry * inv; unit_s[p][2] = rz * inv;
        }
    }
    __syncthreads();

    for (int it = t; it < 2400; it += 256) {
        int p = it / 20, k = it % 20;
        rbf_s[p][k] = __sinf((float)(k + 1) * CUTI * d_s[p]) * inv_s[p];
    }
    __syncthreads();

    int c = 128 + t;
    u64 wr2[10];
#pragma unroll
    for (int q = 0; q < 10; q++)
        wr2[q] = pk2(w_r[(2 * q) * 384 + c], w_r[(2 * q + 1) * 384 + c]);
    float brc = b_r[c];
    float wg0 = (brc < 5.0f) ? 0.5f * (cosf(brc * CUTI) + 1.0f) : 0.0f;

    if (t < 128) {
        float aS[16];
#pragma unroll
        for (int j = 0; j < 16; j++) aS[j] = wg0;
#pragma unroll
        for (int i = 0; i < 15; i++) {
#pragma unroll
            for (int j = i + 1; j < 16; j++) {
                int p = 15 * i - (i * (i - 1)) / 2 + (j - i - 1);
                const ulonglong2* r4 = (const ulonglong2*)rbf_s[p];
                u64 acc = mul2(wr2[0], r4[0].x);
                acc = fma2(wr2[1], r4[0].y, acc);
                ulonglong2 rA = r4[1], rB = r4[2], rC = r4[3], rD = r4[4];
                acc = fma2(wr2[2], rA.x, acc); acc = fma2(wr2[3], rA.y, acc);
                acc = fma2(wr2[4], rB.x, acc); acc = fma2(wr2[5], rB.y, acc);
                acc = fma2(wr2[6], rC.x, acc); acc = fma2(wr2[7], rC.y, acc);
                acc = fma2(wr2[8], rD.x, acc); acc = fma2(wr2[9], rD.y, acc);
                float lo, hi; upk2(lo, hi, acc);
                float lin = lo + hi + brc;
                float wg = (lin < 5.0f) ? 0.5f * (__cosf(lin * CUTI) + 1.0f) : 0.0f;
                aS[i] += wg; aS[j] += wg;
            }
        }
#pragma unroll
        for (int j = 0; j < 16; j++)
            x[(size_t)(mb + j) * 256 + 128 + t] = phi[(size_t)(mb + j) * 256 + t] * aS[j];
    } else {
        int f = t - 128;
        float a0[16], a1[16], a2[16];
#pragma unroll
        for (int j = 0; j < 16; j++) { a0[j] = 0.f; a1[j] = 0.f; a2[j] = 0.f; }
#pragma unroll
        for (int i = 0; i < 15; i++) {
#pragma unroll
            for (int j = i + 1; j < 16; j++) {
                int p = 15 * i - (i * (i - 1)) / 2 + (j - i - 1);
                const ulonglong2* r4 = (const ulonglong2*)rbf_s[p];
                u64 acc = mul2(wr2[0], r4[0].x);
                acc = fma2(wr2[1], r4[0].y, acc);
                ulonglong2 rA = r4[1], rB = r4[2], rC = r4[3], rD = r4[4];
                acc = fma2(wr2[2], rA.x, acc); acc = fma2(wr2[3], rA.y, acc);
                acc = fma2(wr2[4], rB.x, acc); acc = fma2(wr2[5], rB.y, acc);
                acc = fma2(wr2[6], rC.x, acc); acc = fma2(wr2[7], rC.y, acc);
                acc = fma2(wr2[8], rD.x, acc); acc = fma2(wr2[9], rD.y, acc);
                float lo, hi; upk2(lo, hi, acc);
                float lin = lo + hi + brc;
                float wg = (lin < 5.0f) ? 0.5f * (__cosf(lin * CUTI) + 1.0f) : 0.0f;
                float u0 = unit_s[p][0], u1 = unit_s[p][1], u2 = unit_s[p][2];
                a0[j] = fmaf(wg, u0, a0[j]);  a0[i] = fmaf(-wg, u0, a0[i]);
                a1[j] = fmaf(wg, u1, a1[j]);  a1[i] = fmaf(-wg, u1, a1[i]);
                a2[j] = fmaf(wg, u2, a2[j]);  a2[i] = fmaf(-wg, u2, a2[i]);
            }
        }
#pragma unroll
        for (int j = 0; j < 16; j++) {
            float p3 = phi[(size_t)(mb + j) * 256 + 128 + f];
            v1[(size_t)(0 * NN + mb + j) * 128 + f] = p3 * a0[j];
            v1[(size_t)(1 * NN + mb + j) * 128 + f] = p3 * a1[j];
            v1[(size_t)(2 * NN + mb + j) * 128 + f] = p3 * a2[j];
        }
    }
}

// ---------------- final epilogue (float4 vectorized) ----------------------------
__global__ void k_final(const float* __restrict__ m,
                        const float* __restrict__ Uv,
                        const float* __restrict__ Vv,
                        float* __restrict__ out) {
    __shared__ float dvs[3072];
    int t = threadIdx.x;
    size_t i4 = (size_t)blockIdx.x * 256 + t;
    size_t i  = i4 * 4;
    int n = (int)(i >> 7), f = (int)(i & 127);
    const float* mrow = m + (size_t)n * 384 + f;
    float4 avv = *(const float4*)(mrow);
    float4 asv = *(const float4*)(mrow + 128);
    float4 ass = *(const float4*)(mrow + 256);
    float4 u0 = *(const float4*)(Uv + i);
    float4 u1 = *(const float4*)(Uv + (size_t)NN * 128 + i);
    float4 u2 = *(const float4*)(Uv + (size_t)2 * NN * 128 + i);
    float4 v0 = *(const float4*)(Vv + i);
    float4 v1 = *(const float4*)(Vv + (size_t)NN * 128 + i);
    float4 v2 = *(const float4*)(Vv + (size_t)2 * NN * 128 + i);

    float4 os;
    os.x = (u0.x * v0.x + u1.x * v1.x + u2.x * v2.x) * asv.x + ass.x;
    os.y = (u0.y * v0.y + u1.y * v1.y + u2.y * v2.y) * asv.y + ass.y;
    os.z = (u0.z * v0.z + u1.z * v1.z + u2.z * v2.z) * asv.z + ass.z;
    os.w = (u0.w * v0.w + u1.w * v1.w + u2.w * v2.w) * asv.w + ass.w;
    *(float4*)(out + i) = os;

    int li = t * 12;
    dvs[li + 0]  = avv.x * u0.x;  dvs[li + 1]  = avv.x * u1.x;  dvs[li + 2]  = avv.x * u2.x;
    dvs[li + 3]  = avv.y * u0.y;  dvs[li + 4]  = avv.y * u1.y;  dvs[li + 5]  = avv.y * u2.y;
    dvs[li + 6]  = avv.z * u0.z;  dvs[li + 7]  = avv.z * u1.z;  dvs[li + 8]  = avv.z * u2.z;
    dvs[li + 9]  = avv.w * u0.w;  dvs[li + 10] = avv.w * u1.w;  dvs[li + 11] = avv.w * u2.w;
    __syncthreads();

    const float4* dv4 = (const float4*)dvs;
    float* base = out + (size_t)NN * 128 + (size_t)blockIdx.x * 3072;
    *(float4*)(base + t * 4)        = dv4[t];
    *(float4*)(base + 1024 + t * 4) = dv4[256 + t];
    *(float4*)(base + 2048 + t * 4) = dv4[512 + t];
}

// ---------------- launch --------------------------------------------------------
extern "C" void kernel_launch(void* const* d_in, const int* in_sizes, int n_in,
                              void* d_out, int out_size) {
    const int*   atoms = (const int*)  d_in[0];
    const float* pos   = (const float*)d_in[1];
    const float* embed = (const float*)d_in[4];
    const float* w_s1  = (const float*)d_in[5];
    const float* b_s1  = (const float*)d_in[6];
    const float* w_s2  = (const float*)d_in[7];
    const float* b_s2  = (const float*)d_in[8];
    const float* w_r   = (const float*)d_in[9];
    const float* b_r   = (const float*)d_in[10];
    const float* w_u1  = (const float*)d_in[11];
    const float* b_u1  = (const float*)d_in[12];
    const float* w_u2  = (const float*)d_in[13];
    const float* b_u2  = (const float*)d_in[14];
    const float* Uw    = (const float*)d_in[15];
    const float* Ub    = (const float*)d_in[16];
    const float* Vw    = (const float*)d_in[17];
    const float* Vb    = (const float*)d_in[18];
    float* out = (float*)d_out;

    float *phi, *v1, *Uv, *Vv, *x, *mm;
    cudaGetSymbolAddress((void**)&phi, g_phi);
    cudaGetSymbolAddress((void**)&v1,  g_v1);
    cudaGetSymbolAddress((void**)&Uv,  g_Uv);
    cudaGetSymbolAddress((void**)&Vv,  g_Vv);
    cudaGetSymbolAddress((void**)&x,   g_x);
    cudaGetSymbolAddress((void**)&mm,  g_m);

    const int FUSED_SMEM = (64 * APITCH + 64 * BPITCH + 64 * HPITCH) * 2;
    cudaFuncSetAttribute(k_fused_mlp, cudaFuncAttributeMaxDynamicSharedMemorySize,
                         FUSED_SMEM);

    // low-priority side stream for the U-branch: backfills idle SMs only.
    int prLow = 0, prHigh = 0;
    cudaDeviceGetStreamPriorityRange(&prLow, &prHigh);   // prLow = numerically largest
    cudaStream_t s2;
    cudaStreamCreateWithPriority(&s2, cudaStreamNonBlocking, prLow);
    cudaEvent_t evFork, evJoin;
    cudaEventCreateWithFlags(&evFork, cudaEventDisableTiming);
    cudaEventCreateWithFlags(&evJoin, cudaEventDisableTiming);

    // 1) phi = silu(embed[atoms] @ w_s1 + b_s1) @ w_s2[:,128:384] + b_s2[128:384]
    k_fused_mlp<<<NN / 64, 256, FUSED_SMEM>>>(
        embed, atoms, 128, 128, w_s1, b_s1, w_s2 + 128, 384, b_s2 + 128,
        phi, 256, 2, nullptr);
    // 2) edge aggregation (writes v1 planes + x[:,128:] = s1)
    k_edge<<<NN / 16, 256>>>(pos, phi, w_r, b_r, x, v1);
    cudaEventRecord(evFork, 0);

    // 3) critical path first: V-plane GEMMs on the default (higher-prio) stream
    k_gemm_planes<<<dim3(NN / 128, 1, 3), 256>>>(v1, Vw, Vb, Vv);

    // 4) U-plane GEMMs on the low-priority stream; backfill under V tail / MLP2
    cudaStreamWaitEvent(s2, evFork, 0);
    k_gemm_planes<<<dim3(NN / 128, 1, 3), 256, 0, s2>>>(v1, Uw, Ub, Uv);

    // 5) gating MLP (norm fused into staging)
    k_fused_mlp<<<NN / 64, 256, FUSED_SMEM>>>(
        x, nullptr, 256, 256, w_u1, b_u1, w_u2, 384, b_u2,
        mm, 384, 3, Vv);

    // join, then epilogue (vectorized)
    cudaEventRecord(evJoin, s2);
    cudaStreamWaitEvent(0, evJoin, 0);
    k_final<<<NN * 128 / 1024, 256>>>(mm, Uv, Vv, out);

    cudaEventDestroy(evFork);
    cudaEventDestroy(evJoin);
    cudaStreamDestroy(s2);
}